// round 2
// baseline (speedup 1.0000x reference)
#include <cuda_runtime.h>
#include <math_constants.h>
#include <cstdint>

// Problem constants
constexpr int C_  = 64;
constexpr int L_  = 720;
constexpr int D_  = 512;
constexpr int P_  = 336;
constexpr int P2_ = 168;
constexpr int H_  = 512;
constexpr int M_  = 64 * 64;   // B*C = 4096 rows

// Tiling
#define BM 128
#define BN 64
#define BKK 16
#define TM 8
#define TN 4
#define NT 256

enum { EPI_GELU = 0, EPI_TANHPI = 1, EPI_AFFINE = 2, EPI_FINAL = 3 };
enum { A_ROW = 0, A_XBSD = 1 };
enum { V_NONE = 0, V_BUF = 1, V_XBSD = 2 };

// Scratch activations (static device memory; no allocation anywhere)
__device__ __align__(128) float g_h[M_ * H_];
__device__ __align__(128) float g_z[M_ * D_];
__device__ __align__(128) float g_x[M_ * L_];
__device__ __align__(128) float g_y[M_ * P_];
__device__ __align__(128) float g_th[M_ * P2_];

__device__ __forceinline__ float gelu_tanh(float x) {
    // jax.nn.gelu default (approximate=True)
    float x3 = x * x * x;
    return 0.5f * x * (1.0f + tanhf(0.7978845608028654f * (x + 0.044715f * x3)));
}

// One generic tiled GEMM with fused epilogues.
//  EPI_GELU   : out = gelu(A@W)                      (ldw = Nlog)
//  EPI_TANHPI : out = pi*tanh(A@W)                   (ldw = Nlog)
//  EPI_AFFINE : out = vin * exp(tanh(A@Ws)) + A@Wt   (W is (K,2*Nlog); s=cols[0,N), t=cols[N,2N))
//  EPI_FINAL  : full rot/koop/scale/koop^-1/rot^-1 + shift epilogue, transposed store
template <int EPI, int ALD, int VSRC, int KDIM>
__global__ __launch_bounds__(NT)
void gemm_k(const float* __restrict__ A, const float* __restrict__ W,
            const float* __restrict__ Vin, float* __restrict__ Out,
            int Nlog, float vscale,
            const float* __restrict__ Theta,
            const float* __restrict__ Ay, const float* __restrict__ By)
{
    constexpr bool PAIR = (EPI == EPI_AFFINE || EPI == EPI_FINAL);

    __shared__ __align__(16) float As[BKK][BM + 4];
    __shared__ __align__(16) float Ws[BKK][BN];
    __shared__ __align__(16) float Wt[BKK][BN];

    const int tid = threadIdx.x;
    const int tx  = tid & 15;   // N direction (16 threads * TN=4 -> 64)
    const int ty  = tid >> 4;   // M direction (16 threads * TM=8 -> 128)
    const int m0  = blockIdx.x * BM;
    const int n0  = blockIdx.y * BN;
    const int ldw = PAIR ? (2 * Nlog) : Nlog;

    float accS[TM][TN];
    float accT[TM][TN];
#pragma unroll
    for (int i = 0; i < TM; i++)
#pragma unroll
        for (int j = 0; j < TN; j++) { accS[i][j] = 0.f; accT[i][j] = 0.f; }

    // W-loader indexing: each thread loads one float4 per W buffer per k-tile
    const int wk = tid >> 4;          // 0..15 = k within tile
    const int wn = (tid & 15) * 4;    // 0..60 = n within tile
    const bool wok = (n0 + wn) < Nlog;  // Nlog is always a multiple of 4

#pragma unroll 1
    for (int kt = 0; kt < KDIM / BKK; ++kt) {
        const int k0 = kt * BKK;

        // ---- load A tile into As[k][m] ----
        if (ALD == A_ROW) {
#pragma unroll
            for (int it = 0; it < 2; ++it) {
                int f  = tid + it * NT;        // 0..511
                int m  = f >> 2;
                int kv = (f & 3) * 4;
                float4 v = *reinterpret_cast<const float4*>(
                    A + (size_t)(m0 + m) * KDIM + k0 + kv);
                As[kv + 0][m] = v.x; As[kv + 1][m] = v.y;
                As[kv + 2][m] = v.z; As[kv + 3][m] = v.w;
            }
        } else {
            // A[m, l] = x_bsd[b, l, c], m = b*64 + c  (coalesced over m)
#pragma unroll
            for (int it = 0; it < 8; ++it) {
                int idx = tid + it * NT;
                int m = idx & (BM - 1);
                int k = idx >> 7;
                int gm = m0 + m;
                As[k][m] = A[(size_t)(gm >> 6) * (L_ * C_) +
                             (size_t)(k0 + k) * C_ + (gm & (C_ - 1))];
            }
        }

        // ---- load W tile(s) ----
        {
            float4 vs = wok ? *reinterpret_cast<const float4*>(
                                  W + (size_t)(k0 + wk) * ldw + n0 + wn)
                            : make_float4(0.f, 0.f, 0.f, 0.f);
            *reinterpret_cast<float4*>(&Ws[wk][wn]) = vs;
            if (PAIR) {
                float4 vt = wok ? *reinterpret_cast<const float4*>(
                                      W + (size_t)(k0 + wk) * ldw + Nlog + n0 + wn)
                                : make_float4(0.f, 0.f, 0.f, 0.f);
                *reinterpret_cast<float4*>(&Wt[wk][wn]) = vt;
            }
        }
        __syncthreads();

        // ---- MAC ----
#pragma unroll
        for (int k = 0; k < BKK; k++) {
            float a[TM], ws[TN], wt[TN];
            *reinterpret_cast<float4*>(&a[0]) =
                *reinterpret_cast<const float4*>(&As[k][ty * TM]);
            *reinterpret_cast<float4*>(&a[4]) =
                *reinterpret_cast<const float4*>(&As[k][ty * TM + 4]);
            *reinterpret_cast<float4*>(&ws[0]) =
                *reinterpret_cast<const float4*>(&Ws[k][tx * TN]);
            if (PAIR)
                *reinterpret_cast<float4*>(&wt[0]) =
                    *reinterpret_cast<const float4*>(&Wt[k][tx * TN]);
#pragma unroll
            for (int i = 0; i < TM; i++)
#pragma unroll
                for (int j = 0; j < TN; j++) {
                    accS[i][j] = fmaf(a[i], ws[j], accS[i][j]);
                    if (PAIR) accT[i][j] = fmaf(a[i], wt[j], accT[i][j]);
                }
        }
        __syncthreads();
    }

    // ---- epilogue ----
#pragma unroll
    for (int i = 0; i < TM; i++) {
        const int gm = m0 + ty * TM + i;
        if (EPI == EPI_FINAL) {
            const int b = gm >> 6, c = gm & (C_ - 1);
#pragma unroll
            for (int jp = 0; jp < TN / 2; jp++) {
                int n = n0 + tx * TN + jp * 2;   // even column -> pair (n, n+1)
                if (n >= Nlog) continue;
                int p = n >> 1;
                float th = Theta[(size_t)gm * P2_ + p];
                float sn, cs;
                sincosf(th, &sn, &cs);
                float av = Ay[c * P2_ + p], bv = By[c * P2_ + p];
                float rn = rsqrtf(av * av + bv * bv);
                float ca = av * rn, cb = bv * rn;
                float yr = Vin[(size_t)gm * P_ + n];
                float yi = Vin[(size_t)gm * P_ + n + 1];
                // rot(theta)
                float r1 = cs * yr - sn * yi, i1 = sn * yr + cs * yi;
                // koop(a,b)
                float r2 = ca * r1 - cb * i1, i2 = cb * r1 + ca * i1;
                // * scale (elementwise on interleaved)
                float sr = expf(tanhf(accS[i][jp * 2]));
                float si = expf(tanhf(accS[i][jp * 2 + 1]));
                float r3 = r2 * sr, i3 = i2 * si;
                // koop inverse
                float r4 = ca * r3 + cb * i3, i4 = -cb * r3 + ca * i3;
                // rot inverse
                float r5 = cs * r4 + sn * i4, i5 = -sn * r4 + cs * i4;
                // + shift, store transposed (B, P, C)
                Out[((size_t)b * P_ + n) * C_ + c]     = r5 + accT[i][jp * 2];
                Out[((size_t)b * P_ + n + 1) * C_ + c] = i5 + accT[i][jp * 2 + 1];
            }
        } else {
#pragma unroll
            for (int j = 0; j < TN; j++) {
                int n = n0 + tx * TN + j;
                if (n >= Nlog) continue;
                float r;
                if (EPI == EPI_GELU) {
                    r = gelu_tanh(accS[i][j]);
                } else if (EPI == EPI_TANHPI) {
                    r = CUDART_PI_F * tanhf(accS[i][j]);
                } else { // EPI_AFFINE
                    float vin;
                    if (VSRC == V_XBSD)
                        vin = Vin[(size_t)(gm >> 6) * (L_ * C_) +
                                  (size_t)n * C_ + (gm & (C_ - 1))];
                    else
                        vin = Vin[(size_t)gm * Nlog + n] * vscale;
                    r = vin * expf(tanhf(accS[i][j])) + accT[i][j];
                }
                Out[(size_t)gm * Nlog + n] = r;
            }
        }
    }
}

extern "C" void kernel_launch(void* const* d_in, const int* in_sizes, int n_in,
                              void* d_out, int out_size)
{
    (void)in_sizes; (void)n_in; (void)out_size;
    const float* x_bsd   = (const float*)d_in[0];
    const float* z0      = (const float*)d_in[1];
    const float* y0      = (const float*)d_in[2];
    const float* W_h     = (const float*)d_in[3];
    const float* W_ssz   = (const float*)d_in[4];
    const float* W_xz_v2 = (const float*)d_in[5];
    const float* W_xz_v3 = (const float*)d_in[6];
    const float* W_xz_v4 = (const float*)d_in[7];
    const float* W_xz_v5 = (const float*)d_in[8];
    const float* W_zx_v0 = (const float*)d_in[9];
    const float* W_zx_v2 = (const float*)d_in[10];
    const float* W_zx_v3 = (const float*)d_in[11];
    // d_in[12] = W_zx_v5: dead code in the reference (x never read after), skipped
    const float* W_zy_v4 = (const float*)d_in[13];
    const float* W_rot   = (const float*)d_in[14];
    const float* W_koo   = (const float*)d_in[15];
    const float* a_y     = (const float*)d_in[16];
    const float* b_y     = (const float*)d_in[17];
    float* out = (float*)d_out;

    float *h, *z, *x, *y, *th;
    cudaGetSymbolAddress((void**)&h,  g_h);
    cudaGetSymbolAddress((void**)&z,  g_z);
    cudaGetSymbolAddress((void**)&x,  g_x);
    cudaGetSymbolAddress((void**)&y,  g_y);
    cudaGetSymbolAddress((void**)&th, g_th);

    const dim3 blk(NT);
    const int MT = M_ / BM;   // 32

    // 1) h = gelu(x^T @ W_h)                      K=720, N=512
    gemm_k<EPI_GELU, A_XBSD, V_NONE, 720><<<dim3(MT, 8), blk>>>(
        x_bsd, W_h, nullptr, h, H_, 1.f, nullptr, nullptr, nullptr);
    // 2) z1 = affine(0.1*z0 ; h @ W_ssz)          K=512, N=512 pairs
    gemm_k<EPI_AFFINE, A_ROW, V_BUF, 512><<<dim3(MT, 8), blk>>>(
        h, W_ssz, z0, z, D_, 0.1f, nullptr, nullptr, nullptr);
    // 3) x1 = affine(x^T ; z1 @ W_zx_v0)          K=512, N=720 pairs
    gemm_k<EPI_AFFINE, A_ROW, V_XBSD, 512><<<dim3(MT, 12), blk>>>(
        z, W_zx_v0, x_bsd, x, L_, 1.f, nullptr, nullptr, nullptr);
    // 4) z2 = affine(z1 ; x1 @ W_xz_v2)           K=720, N=512 pairs
    gemm_k<EPI_AFFINE, A_ROW, V_BUF, 720><<<dim3(MT, 8), blk>>>(
        x, W_xz_v2, z, z, D_, 1.f, nullptr, nullptr, nullptr);
    // 5) x2 = affine(x1 ; z2 @ W_zx_v2)           K=512, N=720 pairs
    gemm_k<EPI_AFFINE, A_ROW, V_BUF, 512><<<dim3(MT, 12), blk>>>(
        z, W_zx_v2, x, x, L_, 1.f, nullptr, nullptr, nullptr);
    // 6) z3 = affine(z2 ; x2 @ W_xz_v3)
    gemm_k<EPI_AFFINE, A_ROW, V_BUF, 720><<<dim3(MT, 8), blk>>>(
        x, W_xz_v3, z, z, D_, 1.f, nullptr, nullptr, nullptr);
    // 7) x3 = affine(x2 ; z3 @ W_zx_v3)
    gemm_k<EPI_AFFINE, A_ROW, V_BUF, 512><<<dim3(MT, 12), blk>>>(
        z, W_zx_v3, x, x, L_, 1.f, nullptr, nullptr, nullptr);
    // 8) z4 = affine(z3 ; x3 @ W_xz_v4)
    gemm_k<EPI_AFFINE, A_ROW, V_BUF, 720><<<dim3(MT, 8), blk>>>(
        x, W_xz_v4, z, z, D_, 1.f, nullptr, nullptr, nullptr);
    // 9) y1 = affine(0.1*y0 ; z4 @ W_zy_v4)       K=512, N=336 pairs
    gemm_k<EPI_AFFINE, A_ROW, V_BUF, 512><<<dim3(MT, 6), blk>>>(
        z, W_zy_v4, y0, y, P_, 0.1f, nullptr, nullptr, nullptr);
    // 10) z5 = affine(z4 ; x3 @ W_xz_v5)
    gemm_k<EPI_AFFINE, A_ROW, V_BUF, 720><<<dim3(MT, 8), blk>>>(
        x, W_xz_v5, z, z, D_, 1.f, nullptr, nullptr, nullptr);
    // (x4 = affine(x3 ; z5 @ W_zx_v5) is dead -> skipped)
    // 11) theta = pi*tanh(z5 @ W_rot)             K=512, N=168
    gemm_k<EPI_TANHPI, A_ROW, V_NONE, 512><<<dim3(MT, 3), blk>>>(
        z, W_rot, nullptr, th, P2_, 1.f, nullptr, nullptr, nullptr);
    // 12) final: z5 @ W_koo -> scale/shift, full rot/koop chain, transposed store
    gemm_k<EPI_FINAL, A_ROW, V_BUF, 512><<<dim3(MT, 6), blk>>>(
        z, W_koo, y, out, P_, 1.f, th, a_y, b_y);
}

// round 4
// speedup vs baseline: 1.7580x; 1.7580x over previous
#include <cuda_runtime.h>
#include <cuda_bf16.h>
#include <math_constants.h>
#include <cstdint>

// ---------------- problem constants ----------------
constexpr int C_  = 64;
constexpr int L_  = 720;
constexpr int P_  = 336;
constexpr int P2_ = 168;
constexpr int M_  = 4096;   // B*C
constexpr int KPX = 768;    // 720 padded to 64

// ---------------- weight pool offsets (transposed [Nall][Kpad] bf16) -----
constexpr size_t OFF_WH  = 0;                 constexpr size_t SZ_WH  = 512  * 768;
constexpr size_t OFF_SSZ = OFF_WH  + SZ_WH;   constexpr size_t SZ_SSZ = 1024 * 512;
constexpr size_t OFF_XZ2 = OFF_SSZ + SZ_SSZ;  constexpr size_t SZ_XZ  = 1024 * 768;
constexpr size_t OFF_XZ3 = OFF_XZ2 + SZ_XZ;
constexpr size_t OFF_XZ4 = OFF_XZ3 + SZ_XZ;
constexpr size_t OFF_XZ5 = OFF_XZ4 + SZ_XZ;
constexpr size_t OFF_ZX0 = OFF_XZ5 + SZ_XZ;   constexpr size_t SZ_ZX  = 1440 * 512;
constexpr size_t OFF_ZX2 = OFF_ZX0 + SZ_ZX;
constexpr size_t OFF_ZX3 = OFF_ZX2 + SZ_ZX;
constexpr size_t OFF_ZY  = OFF_ZX3 + SZ_ZX;   constexpr size_t SZ_ZY  = 672 * 512;
constexpr size_t OFF_ROT = OFF_ZY  + SZ_ZY;   constexpr size_t SZ_ROT = 168 * 512;
constexpr size_t OFF_KOO = OFF_ROT + SZ_ROT;  constexpr size_t SZ_KOO = 672 * 512;
constexpr size_t POOL    = OFF_KOO + SZ_KOO;

// ---------------- static device scratch ----------------
__device__ __align__(128) __nv_bfloat16 g_wh[POOL];
__device__ __align__(128) __nv_bfloat16 g_wl[POOL];
__device__ __align__(128) float g_x [M_ * KPX];
__device__ __align__(128) float g_h [M_ * 512];
__device__ __align__(128) float g_z [M_ * 512];
__device__ __align__(128) float g_y [M_ * P_];
__device__ __align__(128) float g_th[M_ * P2_];

// ---------------- helpers ----------------
__device__ __forceinline__ uint32_t smem_u32(const void* p) {
    uint32_t a;
    asm("{ .reg .u64 t; cvta.to.shared.u64 t, %1; cvt.u32.u64 %0, t; }" : "=r"(a) : "l"(p));
    return a;
}
__device__ __forceinline__ uint32_t swz(uint32_t o) { return o ^ ((o >> 3) & 0x70); }

__device__ __forceinline__ void ldsm4(uint32_t* r, uint32_t a) {
    asm volatile("ldmatrix.sync.aligned.m8n8.x4.shared.b16 {%0,%1,%2,%3}, [%4];"
                 : "=r"(r[0]), "=r"(r[1]), "=r"(r[2]), "=r"(r[3]) : "r"(a));
}
__device__ __forceinline__ void mma_bf16(float* d, const uint32_t* a, const uint32_t* b) {
    asm volatile(
        "mma.sync.aligned.m16n8k16.row.col.f32.bf16.bf16.f32 "
        "{%0,%1,%2,%3}, {%4,%5,%6,%7}, {%8,%9}, {%0,%1,%2,%3};"
        : "+f"(d[0]), "+f"(d[1]), "+f"(d[2]), "+f"(d[3])
        : "r"(a[0]), "r"(a[1]), "r"(a[2]), "r"(a[3]), "r"(b[0]), "r"(b[1]));
}
__device__ __forceinline__ float gelu_tanh(float x) {
    float x3 = x * x * x;
    return 0.5f * x * (1.0f + tanhf(0.7978845608028654f * (x + 0.044715f * x3)));
}

// ---------------- prep: W [K][Nall] f32 -> [Nall][Kpad] bf16 hi/lo -------
__global__ void convert_w(const float* __restrict__ W, int K, int Nall, int Kpad,
                          __nv_bfloat16* __restrict__ Hi, __nv_bfloat16* __restrict__ Lo)
{
    __shared__ float t[32][33];
    int k0 = blockIdx.x * 32, n0 = blockIdx.y * 32;
    for (int i = threadIdx.y; i < 32; i += 8) {
        int k = k0 + i, n = n0 + threadIdx.x;
        t[i][threadIdx.x] = (k < K && n < Nall) ? W[(size_t)k * Nall + n] : 0.f;
    }
    __syncthreads();
    for (int i = threadIdx.y; i < 32; i += 8) {
        int n = n0 + i, k = k0 + threadIdx.x;
        if (n < Nall) {
            float v = t[threadIdx.x][i];
            __nv_bfloat16 h = __float2bfloat16(v);
            Hi[(size_t)n * Kpad + k] = h;
            Lo[(size_t)n * Kpad + k] = __float2bfloat16(v - __bfloat162float(h));
        }
    }
}

// ---------------- prep: x_bsd [64][720][64] -> xT f32 [4096][768] --------
__global__ void convert_x(const float* __restrict__ X, float* __restrict__ Out)
{
    __shared__ float t[32][33];
    int l0 = blockIdx.x * 32, c0 = blockIdx.y * 32, b = blockIdx.z;
    for (int i = threadIdx.y; i < 32; i += 8) {
        int l = l0 + i;
        t[i][threadIdx.x] = (l < L_) ? X[((size_t)b * L_ + l) * C_ + c0 + threadIdx.x] : 0.f;
    }
    __syncthreads();
    for (int i = threadIdx.y; i < 32; i += 8) {
        int c = c0 + i, l = l0 + threadIdx.x;
        Out[(size_t)(b * 64 + c) * KPX + l] = t[threadIdx.x][i];
    }
}

// ---------------- fused mma.sync GEMM ----------------
enum { EP_GELU = 0, EP_TANHPI = 1, EP_AFF = 2, EP_FINAL = 3 };

// Block tile: M=128 x (RB=64 W-rows). For PAIR epilogues the 64 W-rows are
// 32 s-columns followed by 32 t-columns of the same logical pair block.
template <int EPI>
__global__ __launch_bounds__(256, 2)
void gemm_mma(const float* __restrict__ A, int ldA, int KC,
              const __nv_bfloat16* __restrict__ Wh, const __nv_bfloat16* __restrict__ Wl,
              int ldW, int Nlog,
              const float* __restrict__ Vin, int ldV, float vscale,
              const float* __restrict__ Theta,
              const float* __restrict__ Ay, const float* __restrict__ By,
              float* __restrict__ Out, int ldO)
{
    constexpr bool PAIR = (EPI == EP_AFF || EPI == EP_FINAL);
    constexpr int BN = 32, RB = 64;

    extern __shared__ __align__(16) char smraw[];
    const uint32_t sbRaw = smem_u32(smraw);
    const uint32_t abU   = (sbRaw + 1023u) & ~1023u;
    char* ab = smraw + (abU - sbRaw);

    const int tid = threadIdx.x, wid = tid >> 5, lane = tid & 31;
    const int m0 = blockIdx.x * 128;
    const int n0 = blockIdx.y * (PAIR ? BN : RB);

    char* sAh = ab;          char* sAl = ab + 16384;
    char* sBh = ab + 32768;  char* sBl = ab + 40960;
    const uint32_t uAh = abU, uAl = abU + 16384, uBh = abU + 32768, uBl = abU + 40960;

    const float4* gA = reinterpret_cast<const float4*>(A);
    const uint4* gWh = reinterpret_cast<const uint4*>(Wh);
    const uint4* gWl = reinterpret_cast<const uint4*>(Wl);
    const int ldA4 = ldA >> 2, ldW8 = ldW >> 3;

    const int wm = wid >> 1, wn = wid & 1;
    float acc[2][4][4];
#pragma unroll
    for (int a = 0; a < 2; ++a)
#pragma unroll
        for (int b = 0; b < 4; ++b)
#pragma unroll
            for (int c = 0; c < 4; ++c) acc[a][b][c] = 0.f;

    // per-lane ldmatrix addressing constants
    const uint32_t aoffb = (uint32_t)(wm * 32 + (lane & 15)) * 128;
    const uint32_t boffb = (uint32_t)(wn * 32 + ((lane >> 4) & 1) * 8 + (lane & 7)) * 128;
    const uint32_t lx = (lane & 7) * 16;
    const uint32_t acb = ((lane >> 4) & 1) * 16;
    const uint32_t bcb = ((lane >> 3) & 1) * 16;

    for (int kt = 0; kt < KC; ++kt) {
        // ---- A tile: 128 rows x 64 k f32 -> bf16 hi/lo, swizzled ----
#pragma unroll
        for (int i = 0; i < 4; ++i) {
            int idx = tid + i * 256;
            int r = idx >> 3, q = idx & 7;
            size_t go = (size_t)(m0 + r) * ldA4 + kt * 16 + q * 2;
            float4 v0 = gA[go], v1 = gA[go + 1];
            float f[8] = {v0.x, v0.y, v0.z, v0.w, v1.x, v1.y, v1.z, v1.w};
            uint32_t hw[4], lw[4];
#pragma unroll
            for (int e = 0; e < 4; ++e) {
                __nv_bfloat16 h0 = __float2bfloat16(f[2 * e]);
                __nv_bfloat16 h1 = __float2bfloat16(f[2 * e + 1]);
                __nv_bfloat16 l0 = __float2bfloat16(f[2 * e]     - __bfloat162float(h0));
                __nv_bfloat16 l1 = __float2bfloat16(f[2 * e + 1] - __bfloat162float(h1));
                hw[e] = (uint32_t)__bfloat16_as_ushort(h0) |
                        ((uint32_t)__bfloat16_as_ushort(h1) << 16);
                lw[e] = (uint32_t)__bfloat16_as_ushort(l0) |
                        ((uint32_t)__bfloat16_as_ushort(l1) << 16);
            }
            uint32_t so = swz((uint32_t)(r * 128 + q * 16));
            *reinterpret_cast<uint4*>(sAh + so) = make_uint4(hw[0], hw[1], hw[2], hw[3]);
            *reinterpret_cast<uint4*>(sAl + so) = make_uint4(lw[0], lw[1], lw[2], lw[3]);
        }
        // ---- B tile: 64 W-rows x 64 k bf16 hi/lo, swizzled, guarded ----
#pragma unroll
        for (int i = 0; i < 2; ++i) {
            int idx = tid + i * 256;
            int r = idx >> 3, q = idx & 7;
            int wr; bool ok;
            if (PAIR) {
                if (r < BN) { wr = n0 + r;              ok = (n0 + r) < Nlog; }
                else        { int j = n0 + r - BN; wr = Nlog + j; ok = j < Nlog; }
            } else { wr = n0 + r; ok = wr < Nlog; }
            uint4 z4 = make_uint4(0, 0, 0, 0);
            size_t go = (size_t)wr * ldW8 + kt * 8 + q;
            uint4 vh = ok ? gWh[go] : z4;
            uint4 vl = ok ? gWl[go] : z4;
            uint32_t so = swz((uint32_t)(r * 128 + q * 16));
            *reinterpret_cast<uint4*>(sBh + so) = vh;
            *reinterpret_cast<uint4*>(sBl + so) = vl;
        }
        __syncthreads();

        // ---- 4 x k16 steps, 3-term bf16 split ----
#pragma unroll
        for (int ks = 0; ks < 4; ++ks) {
            uint32_t kb = ks * 32;
            uint32_t axor = (kb + acb) ^ lx;
            uint32_t bxor = (kb + bcb) ^ lx;
            uint32_t ah[2][4], al[2][4], bh[2][4], bl[2][4];
            ldsm4(ah[0], uAh + aoffb + axor);
            ldsm4(ah[1], uAh + aoffb + 2048 + axor);
            ldsm4(bh[0], uBh + boffb + bxor);
            ldsm4(bh[1], uBh + boffb + 2048 + bxor);
#pragma unroll
            for (int mt = 0; mt < 2; ++mt)
#pragma unroll
                for (int nt = 0; nt < 4; ++nt)
                    mma_bf16(acc[mt][nt], ah[mt], &bh[nt >> 1][(nt & 1) * 2]);
            ldsm4(bl[0], uBl + boffb + bxor);
            ldsm4(bl[1], uBl + boffb + 2048 + bxor);
#pragma unroll
            for (int mt = 0; mt < 2; ++mt)
#pragma unroll
                for (int nt = 0; nt < 4; ++nt)
                    mma_bf16(acc[mt][nt], ah[mt], &bl[nt >> 1][(nt & 1) * 2]);
            ldsm4(al[0], uAl + aoffb + axor);
            ldsm4(al[1], uAl + aoffb + 2048 + axor);
#pragma unroll
            for (int mt = 0; mt < 2; ++mt)
#pragma unroll
                for (int nt = 0; nt < 4; ++nt)
                    mma_bf16(acc[mt][nt], al[mt], &bh[nt >> 1][(nt & 1) * 2]);
        }
        __syncthreads();
    }

    // ---- dump accumulators to smem (overwrites stage region) ----
    float* sAcc = reinterpret_cast<float*>(ab);
    {
        const int tr = lane >> 2, tc = (lane & 3) * 2;
#pragma unroll
        for (int mt = 0; mt < 2; ++mt)
#pragma unroll
            for (int nt = 0; nt < 4; ++nt) {
                int row = wm * 32 + mt * 16 + tr, col = wn * 32 + nt * 8 + tc;
                *reinterpret_cast<float2*>(&sAcc[row * 66 + col]) =
                    make_float2(acc[mt][nt][0], acc[mt][nt][1]);
                *reinterpret_cast<float2*>(&sAcc[(row + 8) * 66 + col]) =
                    make_float2(acc[mt][nt][2], acc[mt][nt][3]);
            }
    }
    // ---- stage vin / theta ----
    constexpr int BNp = 33, HW2 = 16, HW2p = 17;
    float* sV = reinterpret_cast<float*>(ab + 34816);
    float* sT = reinterpret_cast<float*>(ab + 51712);
    if (PAIR) {
        for (int r = wid; r < 128; r += 8)
            for (int c = lane; c < BN; c += 32) {
                float v = 0.f;
                if (n0 + c < Nlog) v = Vin[(size_t)(m0 + r) * ldV + n0 + c] * vscale;
                sV[r * BNp + c] = v;
            }
    }
    if (EPI == EP_FINAL) {
        for (int r = wid; r < 128; r += 8)
            for (int c = lane; c < HW2; c += 32) {
                int p = (n0 >> 1) + c;
                sT[r * HW2p + c] = (p < P2_) ? Theta[(size_t)(m0 + r) * P2_ + p] : 0.f;
            }
    }
    __syncthreads();

    // ---- epilogue ----
    const int sub = wid & 3, wg = wid >> 2;
    const int row = sub * 32 + lane;
    const int gm  = m0 + row;

    if (EPI == EP_GELU || EPI == EP_TANHPI) {
#pragma unroll 4
        for (int j = wg * 32; j < wg * 32 + 32; ++j) {
            float a0 = sAcc[row * 66 + j];
            sAcc[row * 66 + j] = (EPI == EP_GELU) ? gelu_tanh(a0)
                                                  : CUDART_PI_F * tanhf(a0);
        }
    } else if (EPI == EP_AFF) {
#pragma unroll 4
        for (int j = wg * 16; j < wg * 16 + 16; ++j) {
            float a0 = sAcc[row * 66 + j], t0 = sAcc[row * 66 + 32 + j];
            sAcc[row * 66 + j] = sV[row * BNp + j] * __expf(tanhf(a0)) + t0;
        }
    } else { // EP_FINAL
        for (int j = wg * 16; j < wg * 16 + 16; j += 2) {
            int n = n0 + j;
            if (n >= Nlog) break;
            float a0 = sAcc[row * 66 + j],      a1 = sAcc[row * 66 + j + 1];
            float t0 = sAcc[row * 66 + 32 + j], t1 = sAcc[row * 66 + 33 + j];
            int p = n >> 1, c = gm & 63, b = gm >> 6;
            float th = sT[row * HW2p + (j >> 1)], sn, cs;
            sincosf(th, &sn, &cs);
            float av = Ay[c * P2_ + p], bv = By[c * P2_ + p];
            float rn = rsqrtf(av * av + bv * bv);
            float ca = av * rn, cb = bv * rn;
            float yr = sV[row * BNp + j], yi = sV[row * BNp + j + 1];
            float r1 = cs * yr - sn * yi, i1 = sn * yr + cs * yi;
            float r2 = ca * r1 - cb * i1, i2 = cb * r1 + ca * i1;
            float r3 = r2 * __expf(tanhf(a0)), i3 = i2 * __expf(tanhf(a1));
            float r4 = ca * r3 + cb * i3,  i4 = -cb * r3 + ca * i3;
            float r5 = cs * r4 + sn * i4,  i5 = -sn * r4 + cs * i4;
            Out[((size_t)b * P_ + n) * C_ + c]     = r5 + t0;
            Out[((size_t)b * P_ + n + 1) * C_ + c] = i5 + t1;
        }
    }
    if (EPI != EP_FINAL) {
        __syncthreads();
        const int Wd = PAIR ? BN : RB;
        for (int r = wid; r < 128; r += 8)
            for (int c = lane; c < Wd; c += 32)
                if (n0 + c < Nlog)
                    Out[(size_t)(m0 + r) * ldO + n0 + c] = sAcc[r * 66 + c];
    }
}

// ---------------- host ----------------
constexpr int SMEMSZ = 61952;

extern "C" void kernel_launch(void* const* d_in, const int* in_sizes, int n_in,
                              void* d_out, int out_size)
{
    (void)in_sizes; (void)n_in; (void)out_size;
    const float* x_bsd = (const float*)d_in[0];
    const float* z0    = (const float*)d_in[1];
    const float* y0    = (const float*)d_in[2];
    const float* a_y   = (const float*)d_in[16];
    const float* b_y   = (const float*)d_in[17];
    float* out = (float*)d_out;

    __nv_bfloat16 *wh, *wl;
    float *x, *h, *z, *y, *th;
    cudaGetSymbolAddress((void**)&wh, g_wh);
    cudaGetSymbolAddress((void**)&wl, g_wl);
    cudaGetSymbolAddress((void**)&x,  g_x);
    cudaGetSymbolAddress((void**)&h,  g_h);
    cudaGetSymbolAddress((void**)&z,  g_z);
    cudaGetSymbolAddress((void**)&y,  g_y);
    cudaGetSymbolAddress((void**)&th, g_th);

    static bool attr_done = false;
    if (!attr_done) {
        cudaFuncSetAttribute(gemm_mma<EP_GELU>,   cudaFuncAttributeMaxDynamicSharedMemorySize, SMEMSZ);
        cudaFuncSetAttribute(gemm_mma<EP_TANHPI>, cudaFuncAttributeMaxDynamicSharedMemorySize, SMEMSZ);
        cudaFuncSetAttribute(gemm_mma<EP_AFF>,    cudaFuncAttributeMaxDynamicSharedMemorySize, SMEMSZ);
        cudaFuncSetAttribute(gemm_mma<EP_FINAL>,  cudaFuncAttributeMaxDynamicSharedMemorySize, SMEMSZ);
        attr_done = true;
    }

    // ---- prep: weight transpose/split + x transpose ----
    struct WS { int idx; int K, Nall, Kpad; size_t off; };
    const WS ws[12] = {
        {3, 720, 512, 768, OFF_WH},  {4, 512, 1024, 512, OFF_SSZ},
        {5, 720, 1024, 768, OFF_XZ2},{6, 720, 1024, 768, OFF_XZ3},
        {7, 720, 1024, 768, OFF_XZ4},{8, 720, 1024, 768, OFF_XZ5},
        {9, 512, 1440, 512, OFF_ZX0},{10,512, 1440, 512, OFF_ZX2},
        {11,512, 1440, 512, OFF_ZX3},{13,512, 672,  512, OFF_ZY},
        {14,512, 168,  512, OFF_ROT},{15,512, 672,  512, OFF_KOO},
    };
    for (int i = 0; i < 12; ++i) {
        dim3 g(ws[i].Kpad / 32, (ws[i].Nall + 31) / 32);
        convert_w<<<g, dim3(32, 8)>>>((const float*)d_in[ws[i].idx],
                                      ws[i].K, ws[i].Nall, ws[i].Kpad,
                                      wh + ws[i].off, wl + ws[i].off);
    }
    convert_x<<<dim3(24, 2, 64), dim3(32, 8)>>>(x_bsd, x);

    // ---- GEMM chain (W_zx_v5 branch dead in the reference: skipped) ----
    gemm_mma<EP_GELU><<<dim3(32, 8), 256, SMEMSZ>>>(
        x, 768, 12, wh + OFF_WH, wl + OFF_WH, 768, 512,
        nullptr, 0, 0.f, nullptr, nullptr, nullptr, h, 512);
    gemm_mma<EP_AFF><<<dim3(32, 16), 256, SMEMSZ>>>(
        h, 512, 8, wh + OFF_SSZ, wl + OFF_SSZ, 512, 512,
        z0, 512, 0.1f, nullptr, nullptr, nullptr, z, 512);
    gemm_mma<EP_AFF><<<dim3(32, 23), 256, SMEMSZ>>>(
        z, 512, 8, wh + OFF_ZX0, wl + OFF_ZX0, 512, 720,
        x, 768, 1.f, nullptr, nullptr, nullptr, x, 768);
    gemm_mma<EP_AFF><<<dim3(32, 16), 256, SMEMSZ>>>(
        x, 768, 12, wh + OFF_XZ2, wl + OFF_XZ2, 768, 512,
        z, 512, 1.f, nullptr, nullptr, nullptr, z, 512);
    gemm_mma<EP_AFF><<<dim3(32, 23), 256, SMEMSZ>>>(
        z, 512, 8, wh + OFF_ZX2, wl + OFF_ZX2, 512, 720,
        x, 768, 1.f, nullptr, nullptr, nullptr, x, 768);
    gemm_mma<EP_AFF><<<dim3(32, 16), 256, SMEMSZ>>>(
        x, 768, 12, wh + OFF_XZ3, wl + OFF_XZ3, 768, 512,
        z, 512, 1.f, nullptr, nullptr, nullptr, z, 512);
    gemm_mma<EP_AFF><<<dim3(32, 23), 256, SMEMSZ>>>(
        z, 512, 8, wh + OFF_ZX3, wl + OFF_ZX3, 512, 720,
        x, 768, 1.f, nullptr, nullptr, nullptr, x, 768);
    gemm_mma<EP_AFF><<<dim3(32, 16), 256, SMEMSZ>>>(
        x, 768, 12, wh + OFF_XZ4, wl + OFF_XZ4, 768, 512,
        z, 512, 1.f, nullptr, nullptr, nullptr, z, 512);
    gemm_mma<EP_AFF><<<dim3(32, 11), 256, SMEMSZ>>>(
        z, 512, 8, wh + OFF_ZY, wl + OFF_ZY, 512, 336,
        y0, 336, 0.1f, nullptr, nullptr, nullptr, y, 336);
    gemm_mma<EP_AFF><<<dim3(32, 16), 256, SMEMSZ>>>(
        x, 768, 12, wh + OFF_XZ5, wl + OFF_XZ5, 768, 512,
        z, 512, 1.f, nullptr, nullptr, nullptr, z, 512);
    gemm_mma<EP_TANHPI><<<dim3(32, 3), 256, SMEMSZ>>>(
        z, 512, 8, wh + OFF_ROT, wl + OFF_ROT, 512, 168,
        nullptr, 0, 0.f, nullptr, nullptr, nullptr, th, 168);
    gemm_mma<EP_FINAL><<<dim3(32, 11), 256, SMEMSZ>>>(
        z, 512, 8, wh + OFF_KOO, wl + OFF_KOO, 512, 336,
        y, 336, 1.f, th, a_y, b_y, out, 0);
}